// round 1
// baseline (speedup 1.0000x reference)
#include <cuda_runtime.h>
#include <math.h>

#define B_ 8
#define N_ 1024
#define C_ 768
#define H_ 12
#define D_ 64
#define BH_ (B_*H_)

// Scratch (device globals — no allocation allowed)
__device__ float g_q [BH_*N_*D_];   // [B,H,N,D]
__device__ float g_k [BH_*N_*D_];
__device__ float g_v [BH_*N_*D_];
__device__ float g_ao[B_*N_*C_];    // attention output in [B,N,C]

// ---------------------------------------------------------------------------
// Tiled SGEMM: Y[m,c] = sum_k A[m,k] * W[c,k]   (A row-major [M,K], W [Ncol,K])
// 128x128 block tile, BK=16, 256 threads, 8x8 per thread.
// MODE 0: scatter epilogue into g_q/g_k/g_v ([B,H,N,D] layout, c -> (s,h,d))
// MODE 1: A := g_ao, plain row-major store to Y
// ---------------------------------------------------------------------------
#define GPITCH 132

template<int MODE>
__global__ __launch_bounds__(256)
void sgemm_kernel(const float* __restrict__ A, const float* __restrict__ W,
                  float* __restrict__ Y, int M, int Ncol, int K)
{
    __shared__ float As[16*GPITCH];
    __shared__ float Ws[16*GPITCH];

    const int tid = threadIdx.x;
    const int tr  = tid >> 4;        // 0..15 (row group)
    const int tc  = tid & 15;        // 0..15 (col group)
    const int bm  = blockIdx.y * 128;
    const int bn  = blockIdx.x * 128;

    const int lr  = tid >> 2;        // 0..63 load row
    const int lk  = (tid & 3) << 2;  // 0,4,8,12 load k-offset

    if (MODE == 1) A = g_ao;

    const float* Aptr = A + (size_t)(bm + lr) * K + lk;
    const float* Wptr = W + (size_t)(bn + lr) * K + lk;

    float acc[8][8];
    #pragma unroll
    for (int i = 0; i < 8; i++)
        #pragma unroll
        for (int j = 0; j < 8; j++) acc[i][j] = 0.f;

    for (int k0 = 0; k0 < K; k0 += 16) {
        float4 a0 = *(const float4*)(Aptr);
        float4 a1 = *(const float4*)(Aptr + (size_t)64 * K);
        float4 w0 = *(const float4*)(Wptr);
        float4 w1 = *(const float4*)(Wptr + (size_t)64 * K);
        __syncthreads();
        As[(lk+0)*GPITCH + lr]      = a0.x;
        As[(lk+1)*GPITCH + lr]      = a0.y;
        As[(lk+2)*GPITCH + lr]      = a0.z;
        As[(lk+3)*GPITCH + lr]      = a0.w;
        As[(lk+0)*GPITCH + lr + 64] = a1.x;
        As[(lk+1)*GPITCH + lr + 64] = a1.y;
        As[(lk+2)*GPITCH + lr + 64] = a1.z;
        As[(lk+3)*GPITCH + lr + 64] = a1.w;
        Ws[(lk+0)*GPITCH + lr]      = w0.x;
        Ws[(lk+1)*GPITCH + lr]      = w0.y;
        Ws[(lk+2)*GPITCH + lr]      = w0.z;
        Ws[(lk+3)*GPITCH + lr]      = w0.w;
        Ws[(lk+0)*GPITCH + lr + 64] = w1.x;
        Ws[(lk+1)*GPITCH + lr + 64] = w1.y;
        Ws[(lk+2)*GPITCH + lr + 64] = w1.z;
        Ws[(lk+3)*GPITCH + lr + 64] = w1.w;
        __syncthreads();

        #pragma unroll
        for (int kk = 0; kk < 16; kk++) {
            float4 af0 = *(const float4*)&As[kk*GPITCH + tr*8];
            float4 af1 = *(const float4*)&As[kk*GPITCH + tr*8 + 4];
            float4 wf0 = *(const float4*)&Ws[kk*GPITCH + tc*8];
            float4 wf1 = *(const float4*)&Ws[kk*GPITCH + tc*8 + 4];
            float a[8] = {af0.x, af0.y, af0.z, af0.w, af1.x, af1.y, af1.z, af1.w};
            float w[8] = {wf0.x, wf0.y, wf0.z, wf0.w, wf1.x, wf1.y, wf1.z, wf1.w};
            #pragma unroll
            for (int i = 0; i < 8; i++)
                #pragma unroll
                for (int j = 0; j < 8; j++)
                    acc[i][j] += a[i] * w[j];
        }
        Aptr += 16;
        Wptr += 16;
    }

    #pragma unroll
    for (int i = 0; i < 8; i++) {
        const int m = bm + tr*8 + i;
        const int b = m >> 10;        // / N_
        const int n = m & 1023;
        #pragma unroll
        for (int j = 0; j < 8; j++) {
            const int c = bn + tc*8 + j;
            const float val = acc[i][j];
            if (MODE == 1) {
                Y[(size_t)m * Ncol + c] = val;
            } else {
                const int s = c / C_;
                const int w = c - s * C_;
                const int h = w >> 6;
                const int d = w & 63;
                const int idx = ((b*H_ + h)*N_ + n)*D_ + d;
                if (s == 0)      g_q[idx] = val;
                else if (s == 1) g_k[idx] = val;
                else             g_v[idx] = val;
            }
        }
    }
}

// ---------------------------------------------------------------------------
// Per-head LayerNorm over D=64 (gamma=1, beta=0, biased var). q rows also *SCALE.
// One warp per row, 2 elems/lane.
// ---------------------------------------------------------------------------
__global__ __launch_bounds__(256)
void ln_kernel()
{
    const int warp = (blockIdx.x * blockDim.x + threadIdx.x) >> 5;
    const int lane = threadIdx.x & 31;
    const int nrows = BH_ * N_;               // 98304
    if (warp >= 2 * nrows) return;

    float* buf  = (warp < nrows) ? g_q : g_k;
    const float scale = (warp < nrows) ? 0.125f : 1.0f;   // D^-0.5 = 1/8
    const int row = (warp < nrows) ? warp : warp - nrows;

    float2 x = *(float2*)&buf[(size_t)row*64 + lane*2];
    float sum = x.x + x.y;
    #pragma unroll
    for (int o = 16; o > 0; o >>= 1) sum += __shfl_xor_sync(0xffffffffu, sum, o);
    const float mean = sum * (1.0f/64.0f);
    const float dx = x.x - mean, dy = x.y - mean;
    float vs = dx*dx + dy*dy;
    #pragma unroll
    for (int o = 16; o > 0; o >>= 1) vs += __shfl_xor_sync(0xffffffffu, vs, o);
    const float inv = rsqrtf(vs * (1.0f/64.0f) + 1e-5f) * scale;
    float2 out; out.x = dx * inv; out.y = dy * inv;
    *(float2*)&buf[(size_t)row*64 + lane*2] = out;
}

// ---------------------------------------------------------------------------
// Flash attention, fp32. One block = 64 query rows of one (b,h).
// 256 threads as 16x16; each thread 4 rows x 4 cols microtile.
// Loops over 16 key tiles of 64, online softmax, writes to g_ao [B,N,C].
// ---------------------------------------------------------------------------
#define FP 68   // padded pitch for q/k/p tiles

__global__ __launch_bounds__(256)
void flash_kernel()
{
    extern __shared__ float smem[];
    float* qs = smem;                 // [64][FP]
    float* ks = qs + 64*FP;           // [64][FP]
    float* ps = ks + 64*FP;           // [64][FP]
    float* vs = ps + 64*FP;           // [64][64]

    const int bh    = blockIdx.y;     // 0..95
    const int qtile = blockIdx.x;     // 0..15
    const int b = bh / H_;
    const int h = bh - b * H_;

    const float* Q  = g_q + (size_t)bh * N_ * D_ + (size_t)qtile * 64 * D_;
    const float* Kp = g_k + (size_t)bh * N_ * D_;
    const float* Vp = g_v + (size_t)bh * N_ * D_;

    const int tid = threadIdx.x;
    const int ty = tid >> 4, tx = tid & 15;

    // load q tile (scalar stores, padded pitch)
    for (int i = tid; i < 64*16; i += 256) {
        const int r = i >> 4, cv = (i & 15) << 2;
        float4 v4 = *(const float4*)(Q + r*64 + cv);
        qs[r*FP + cv + 0] = v4.x;
        qs[r*FP + cv + 1] = v4.y;
        qs[r*FP + cv + 2] = v4.z;
        qs[r*FP + cv + 3] = v4.w;
    }

    float oacc[4][4];
    float mi[4], li[4];
    #pragma unroll
    for (int i = 0; i < 4; i++) {
        mi[i] = -3.0e38f; li[i] = 0.f;
        #pragma unroll
        for (int d = 0; d < 4; d++) oacc[i][d] = 0.f;
    }

    for (int j = 0; j < 16; j++) {
        __syncthreads();   // previous iteration done with ks/vs/ps
        for (int i = tid; i < 64*16; i += 256) {
            const int r = i >> 4, cv = (i & 15) << 2;
            float4 k4 = *(const float4*)(Kp + (size_t)j*64*64 + r*64 + cv);
            ks[r*FP + cv + 0] = k4.x;
            ks[r*FP + cv + 1] = k4.y;
            ks[r*FP + cv + 2] = k4.z;
            ks[r*FP + cv + 3] = k4.w;
            float4 v4 = *(const float4*)(Vp + (size_t)j*64*64 + r*64 + cv);
            *(float4*)&vs[r*64 + cv] = v4;
        }
        __syncthreads();

        // S = q @ k^T  (4x4 microtile)
        float s[4][4];
        #pragma unroll
        for (int i = 0; i < 4; i++)
            #pragma unroll
            for (int jj = 0; jj < 4; jj++) s[i][jj] = 0.f;

        #pragma unroll 4
        for (int kk = 0; kk < 64; kk++) {
            float qr[4], kc[4];
            #pragma unroll
            for (int i = 0; i < 4; i++)  qr[i]  = qs[(ty*4+i)*FP + kk];
            #pragma unroll
            for (int jj = 0; jj < 4; jj++) kc[jj] = ks[(tx*4+jj)*FP + kk];
            #pragma unroll
            for (int i = 0; i < 4; i++)
                #pragma unroll
                for (int jj = 0; jj < 4; jj++)
                    s[i][jj] += qr[i] * kc[jj];
        }

        // online softmax per row
        #pragma unroll
        for (int i = 0; i < 4; i++) {
            float mx = fmaxf(fmaxf(s[i][0], s[i][1]), fmaxf(s[i][2], s[i][3]));
            #pragma unroll
            for (int o = 8; o > 0; o >>= 1)
                mx = fmaxf(mx, __shfl_xor_sync(0xffffffffu, mx, o, 16));
            const float mnew = fmaxf(mi[i], mx);
            const float corr = __expf(mi[i] - mnew);
            mi[i] = mnew;
            float rs = 0.f;
            #pragma unroll
            for (int jj = 0; jj < 4; jj++) {
                const float p = __expf(s[i][jj] - mnew);
                s[i][jj] = p;
                rs += p;
            }
            #pragma unroll
            for (int o = 8; o > 0; o >>= 1)
                rs += __shfl_xor_sync(0xffffffffu, rs, o, 16);
            li[i] = li[i] * corr + rs;
            #pragma unroll
            for (int d = 0; d < 4; d++) oacc[i][d] *= corr;
            #pragma unroll
            for (int jj = 0; jj < 4; jj++)
                ps[(ty*4+i)*FP + tx*4 + jj] = s[i][jj];
        }
        __syncthreads();

        // O += P @ V
        #pragma unroll 4
        for (int kc = 0; kc < 64; kc++) {
            float pr[4];
            #pragma unroll
            for (int i = 0; i < 4; i++) pr[i] = ps[(ty*4+i)*FP + kc];
            float4 vv = *(const float4*)&vs[kc*64 + tx*4];
            #pragma unroll
            for (int i = 0; i < 4; i++) {
                oacc[i][0] += pr[i] * vv.x;
                oacc[i][1] += pr[i] * vv.y;
                oacc[i][2] += pr[i] * vv.z;
                oacc[i][3] += pr[i] * vv.w;
            }
        }
    }

    // epilogue: O / l, write to g_ao [B,N,C] with c = h*64 + d
    #pragma unroll
    for (int i = 0; i < 4; i++) {
        const float invl = 1.0f / li[i];
        const int n = qtile*64 + ty*4 + i;
        float* dst = g_ao + ((size_t)b*N_ + n)*C_ + h*64 + tx*4;
        float4 o4;
        o4.x = oacc[i][0] * invl;
        o4.y = oacc[i][1] * invl;
        o4.z = oacc[i][2] * invl;
        o4.w = oacc[i][3] * invl;
        *(float4*)dst = o4;
    }
}

// ---------------------------------------------------------------------------
extern "C" void kernel_launch(void* const* d_in, const int* in_sizes, int n_in,
                              void* d_out, int out_size)
{
    const float* x     = (const float*)d_in[0];   // [B,N,C]
    const float* wqkv  = (const float*)d_in[1];   // [3C,C]
    const float* wproj = (const float*)d_in[2];   // [C,C]
    float* out = (float*)d_out;                   // [B,N,C]

    // 1) QKV GEMM: [8192,768] x [2304,768]^T, scatter into q/k/v [B,H,N,D]
    {
        dim3 grid(3*C_/128, (B_*N_)/128);   // (18, 64)
        sgemm_kernel<0><<<grid, 256>>>(x, wqkv, nullptr, B_*N_, 3*C_, C_);
    }

    // 2) Per-head LayerNorm on q (with *SCALE) and k
    {
        const int warps = 2 * BH_ * N_;          // 196608
        const int blocks = (warps * 32 + 255) / 256;
        ln_kernel<<<blocks, 256>>>();
    }

    // 3) Flash attention -> g_ao [B,N,C]
    {
        const int smem_bytes = (3*64*FP + 64*64) * (int)sizeof(float);  // ~68.6 KB
        cudaFuncSetAttribute(flash_kernel,
                             cudaFuncAttributeMaxDynamicSharedMemorySize, smem_bytes);
        dim3 grid(N_/64, BH_);   // (16, 96)
        flash_kernel<<<grid, 256, smem_bytes>>>();
    }

    // 4) Output projection: [8192,768] x [768,768]^T
    {
        dim3 grid(C_/128, (B_*N_)/128);     // (6, 64)
        sgemm_kernel<1><<<grid, 256>>>(nullptr, wproj, out, B_*N_, C_, C_);
    }
}

// round 2
// speedup vs baseline: 2.7652x; 2.7652x over previous
#include <cuda_runtime.h>
#include <math.h>
#include <stdint.h>

#define B_ 8
#define N_ 1024
#define C_ 768
#define H_ 12
#define D_ 64
#define BH_ (B_*H_)

// Scratch (device globals — no allocation allowed)
__device__ float g_q [BH_*N_*D_];   // [B,H,N,D]
__device__ float g_k [BH_*N_*D_];
__device__ float g_v [BH_*N_*D_];
__device__ float g_ao[B_*N_*C_];    // attention output in [B,N,C]

// ---------------------------------------------------------------------------
// tf32 helpers
// ---------------------------------------------------------------------------
__device__ __forceinline__ uint32_t f2tf(float f) {
    uint32_t u;
    asm("cvt.rna.tf32.f32 %0, %1;" : "=r"(u) : "f"(f));
    return u;
}

// D = A(16x8) * B(8x8) + D, tf32, fp32 accum
__device__ __forceinline__ void mma8(float* c, const uint32_t* a, const uint32_t* b) {
    asm volatile(
        "mma.sync.aligned.m16n8k8.row.col.f32.tf32.tf32.f32 "
        "{%0,%1,%2,%3},{%4,%5,%6,%7},{%8,%9},{%0,%1,%2,%3};"
        : "+f"(c[0]), "+f"(c[1]), "+f"(c[2]), "+f"(c[3])
        : "r"(a[0]), "r"(a[1]), "r"(a[2]), "r"(a[3]), "r"(b[0]), "r"(b[1]));
}

// ---------------------------------------------------------------------------
// tf32 GEMM: Y[m,c] = sum_k A[m,k] * W[c,k]
// BM=BN=128, BK=16, 256 threads = 8 warps (2x4), warp tile 64x32.
// MODE 0: scatter into g_q/g_k/g_v;  MODE 1: A := g_ao, row-major store.
// ---------------------------------------------------------------------------
#define KP 20   // smem pitch (conflict-free for frag loads)

template<int MODE>
__global__ __launch_bounds__(256)
void gemm_tf32(const float* __restrict__ A, const float* __restrict__ W,
               float* __restrict__ Y, int M, int Ncol, int K)
{
    __shared__ float As[128*KP];
    __shared__ float Ws[128*KP];

    const int tid  = threadIdx.x;
    const int warp = tid >> 5, lane = tid & 31;
    const int g    = lane >> 2, tig = lane & 3;
    const int wm   = (warp >> 2) * 64;
    const int wn   = (warp & 3)  * 32;
    const int bm   = blockIdx.y * 128;
    const int bn   = blockIdx.x * 128;

    if (MODE == 1) A = g_ao;

    const int lr = tid >> 1;        // 0..127
    const int lc = (tid & 1) * 8;   // 0 or 8

    const float* Ap = A + (size_t)(bm + lr) * K + lc;
    const float* Wp = W + (size_t)(bn + lr) * K + lc;

    float acc[4][4][4];
    #pragma unroll
    for (int i = 0; i < 4; i++)
        #pragma unroll
        for (int j = 0; j < 4; j++)
            #pragma unroll
            for (int e = 0; e < 4; e++) acc[i][j][e] = 0.f;

    float4 ra0 = *(const float4*)Ap;
    float4 ra1 = *(const float4*)(Ap + 4);
    float4 rw0 = *(const float4*)Wp;
    float4 rw1 = *(const float4*)(Wp + 4);

    for (int k0 = 0; k0 < K; k0 += 16) {
        __syncthreads();
        *(float4*)&As[lr*KP + lc]     = ra0;
        *(float4*)&As[lr*KP + lc + 4] = ra1;
        *(float4*)&Ws[lr*KP + lc]     = rw0;
        *(float4*)&Ws[lr*KP + lc + 4] = rw1;
        __syncthreads();

        if (k0 + 16 < K) {
            Ap += 16; Wp += 16;
            ra0 = *(const float4*)Ap;
            ra1 = *(const float4*)(Ap + 4);
            rw0 = *(const float4*)Wp;
            rw1 = *(const float4*)(Wp + 4);
        }

        #pragma unroll
        for (int kk = 0; kk < 16; kk += 8) {
            uint32_t af[4][4];
            #pragma unroll
            for (int mf = 0; mf < 4; mf++) {
                const int r0 = wm + mf*16 + g;
                af[mf][0] = f2tf(As[ r0     *KP + kk + tig]);
                af[mf][1] = f2tf(As[(r0 + 8)*KP + kk + tig]);
                af[mf][2] = f2tf(As[ r0     *KP + kk + tig + 4]);
                af[mf][3] = f2tf(As[(r0 + 8)*KP + kk + tig + 4]);
            }
            uint32_t bf[4][2];
            #pragma unroll
            for (int nf = 0; nf < 4; nf++) {
                const int nr = wn + nf*8 + g;
                bf[nf][0] = f2tf(Ws[nr*KP + kk + tig]);
                bf[nf][1] = f2tf(Ws[nr*KP + kk + tig + 4]);
            }
            #pragma unroll
            for (int mf = 0; mf < 4; mf++)
                #pragma unroll
                for (int nf = 0; nf < 4; nf++)
                    mma8(acc[mf][nf], af[mf], bf[nf]);
        }
    }

    // epilogue
    #pragma unroll
    for (int mf = 0; mf < 4; mf++) {
        #pragma unroll
        for (int rr = 0; rr < 2; rr++) {
            const int m = bm + wm + mf*16 + g + rr*8;
            const int b = m >> 10;
            const int n = m & 1023;
            #pragma unroll
            for (int nf = 0; nf < 4; nf++) {
                const int c = bn + wn + nf*8 + 2*tig;
                float2 v2;
                v2.x = acc[mf][nf][rr*2 + 0];
                v2.y = acc[mf][nf][rr*2 + 1];
                if (MODE == 1) {
                    *(float2*)&Y[(size_t)m * Ncol + c] = v2;
                } else {
                    const int s = c / C_;
                    const int w = c - s * C_;
                    const int h = w >> 6;
                    const int d = w & 63;
                    const int idx = ((b*H_ + h)*N_ + n)*D_ + d;
                    if (s == 0)      *(float2*)&g_q[idx] = v2;
                    else if (s == 1) *(float2*)&g_k[idx] = v2;
                    else             *(float2*)&g_v[idx] = v2;
                }
            }
        }
    }
}

// ---------------------------------------------------------------------------
// Per-head LayerNorm over D=64. q rows also *SCALE (=1/8).
// ---------------------------------------------------------------------------
__global__ __launch_bounds__(256)
void ln_kernel()
{
    const int warp = (blockIdx.x * blockDim.x + threadIdx.x) >> 5;
    const int lane = threadIdx.x & 31;
    const int nrows = BH_ * N_;
    if (warp >= 2 * nrows) return;

    float* buf  = (warp < nrows) ? g_q : g_k;
    const float scale = (warp < nrows) ? 0.125f : 1.0f;
    const int row = (warp < nrows) ? warp : warp - nrows;

    float2 x = *(float2*)&buf[(size_t)row*64 + lane*2];
    float sum = x.x + x.y;
    #pragma unroll
    for (int o = 16; o > 0; o >>= 1) sum += __shfl_xor_sync(0xffffffffu, sum, o);
    const float mean = sum * (1.0f/64.0f);
    const float dx = x.x - mean, dy = x.y - mean;
    float vs = dx*dx + dy*dy;
    #pragma unroll
    for (int o = 16; o > 0; o >>= 1) vs += __shfl_xor_sync(0xffffffffu, vs, o);
    const float inv = rsqrtf(vs * (1.0f/64.0f) + 1e-5f) * scale;
    float2 out; out.x = dx * inv; out.y = dy * inv;
    *(float2*)&buf[(size_t)row*64 + lane*2] = out;
}

// ---------------------------------------------------------------------------
// Flash attention, tf32 mma. One block = 64 q rows of one (b,h), 128 threads.
// Warp w owns q rows [16w, 16w+16). Loops 16 KV tiles of 64.
// ---------------------------------------------------------------------------
#define FPT 68  // smem pitch (conflict-free: 68 mod 32 = 4)

__global__ __launch_bounds__(128)
void flash_tf32()
{
    extern __shared__ float smem[];
    float* qs  = smem;               // [64][FPT]
    float* ks  = qs  + 64*FPT;       // [64][FPT]  K tile [key][d]
    float* vts = ks  + 64*FPT;       // [64][FPT]  V^T   [d][key]
    float* ps  = vts + 64*FPT;       // [64][FPT]  P     [qrow][key]

    const int bh    = blockIdx.y;
    const int qtile = blockIdx.x;
    const int b = bh / H_;
    const int h = bh - b * H_;

    const float* Q  = g_q + (size_t)bh * N_ * D_ + (size_t)qtile * 64 * D_;
    const float* Kp = g_k + (size_t)bh * N_ * D_;
    const float* Vp = g_v + (size_t)bh * N_ * D_;

    const int tid  = threadIdx.x;
    const int warp = tid >> 5, lane = tid & 31;
    const int g    = lane >> 2, tig = lane & 3;
    const int wband = warp * 16;

    // load q tile
    for (int i = tid; i < 64*16; i += 128) {
        const int r = i >> 4, cv = (i & 15) << 2;
        *(float4*)&qs[r*FPT + cv] = *(const float4*)(Q + r*64 + cv);
    }
    __syncthreads();

    // hoist Q A-frags (reused for all 16 KV tiles)
    uint32_t qa[8][4];
    #pragma unroll
    for (int kf = 0; kf < 8; kf++) {
        const int r0 = wband + g;
        qa[kf][0] = f2tf(qs[ r0     *FPT + kf*8 + tig]);
        qa[kf][1] = f2tf(qs[(r0 + 8)*FPT + kf*8 + tig]);
        qa[kf][2] = f2tf(qs[ r0     *FPT + kf*8 + tig + 4]);
        qa[kf][3] = f2tf(qs[(r0 + 8)*FPT + kf*8 + tig + 4]);
    }

    float o[8][4];
    #pragma unroll
    for (int nf = 0; nf < 8; nf++)
        #pragma unroll
        for (int e = 0; e < 4; e++) o[nf][e] = 0.f;
    float m0 = -1e30f, m1 = -1e30f, l0 = 0.f, l1 = 0.f;

    for (int j = 0; j < 16; j++) {
        __syncthreads();  // previous iter done with ks/vts
        for (int i = tid; i < 64*16; i += 128) {
            const int r = i >> 4, cv = (i & 15) << 2;
            *(float4*)&ks[r*FPT + cv] =
                *(const float4*)(Kp + (size_t)j*4096 + r*64 + cv);
            float4 v4 = *(const float4*)(Vp + (size_t)j*4096 + r*64 + cv);
            vts[(cv+0)*FPT + r] = v4.x;
            vts[(cv+1)*FPT + r] = v4.y;
            vts[(cv+2)*FPT + r] = v4.z;
            vts[(cv+3)*FPT + r] = v4.w;
        }
        __syncthreads();

        // S = Q @ K^T   (warp: 16 rows x 64 cols)
        float s[8][4];
        #pragma unroll
        for (int nf = 0; nf < 8; nf++)
            #pragma unroll
            for (int e = 0; e < 4; e++) s[nf][e] = 0.f;

        #pragma unroll
        for (int kf = 0; kf < 8; kf++) {
            #pragma unroll
            for (int nf = 0; nf < 8; nf++) {
                uint32_t bfr[2];
                bfr[0] = f2tf(ks[(nf*8 + g)*FPT + kf*8 + tig]);
                bfr[1] = f2tf(ks[(nf*8 + g)*FPT + kf*8 + tig + 4]);
                mma8(s[nf], qa[kf], bfr);
            }
        }

        // online softmax (rows r0 = wband+g, r1 = r0+8)
        float mx0 = -1e30f, mx1 = -1e30f;
        #pragma unroll
        for (int nf = 0; nf < 8; nf++) {
            mx0 = fmaxf(mx0, fmaxf(s[nf][0], s[nf][1]));
            mx1 = fmaxf(mx1, fmaxf(s[nf][2], s[nf][3]));
        }
        mx0 = fmaxf(mx0, __shfl_xor_sync(0xffffffffu, mx0, 1));
        mx0 = fmaxf(mx0, __shfl_xor_sync(0xffffffffu, mx0, 2));
        mx1 = fmaxf(mx1, __shfl_xor_sync(0xffffffffu, mx1, 1));
        mx1 = fmaxf(mx1, __shfl_xor_sync(0xffffffffu, mx1, 2));

        const float mn0 = fmaxf(m0, mx0);
        const float mn1 = fmaxf(m1, mx1);
        const float corr0 = __expf(m0 - mn0);
        const float corr1 = __expf(m1 - mn1);
        m0 = mn0; m1 = mn1;

        float rs0 = 0.f, rs1 = 0.f;
        #pragma unroll
        for (int nf = 0; nf < 8; nf++) {
            const float p0 = __expf(s[nf][0] - mn0);
            const float p1 = __expf(s[nf][1] - mn0);
            const float p2 = __expf(s[nf][2] - mn1);
            const float p3 = __expf(s[nf][3] - mn1);
            rs0 += p0 + p1;
            rs1 += p2 + p3;
            float2 w0; w0.x = p0; w0.y = p1;
            float2 w1; w1.x = p2; w1.y = p3;
            *(float2*)&ps[(wband + g    )*FPT + nf*8 + 2*tig] = w0;
            *(float2*)&ps[(wband + g + 8)*FPT + nf*8 + 2*tig] = w1;
        }
        rs0 += __shfl_xor_sync(0xffffffffu, rs0, 1);
        rs0 += __shfl_xor_sync(0xffffffffu, rs0, 2);
        rs1 += __shfl_xor_sync(0xffffffffu, rs1, 1);
        rs1 += __shfl_xor_sync(0xffffffffu, rs1, 2);
        l0 = l0 * corr0 + rs0;
        l1 = l1 * corr1 + rs1;

        #pragma unroll
        for (int nf = 0; nf < 8; nf++) {
            o[nf][0] *= corr0; o[nf][1] *= corr0;
            o[nf][2] *= corr1; o[nf][3] *= corr1;
        }
        __syncwarp();

        // O += P @ V
        #pragma unroll
        for (int kf = 0; kf < 8; kf++) {
            uint32_t pa[4];
            pa[0] = f2tf(ps[(wband + g    )*FPT + kf*8 + tig]);
            pa[1] = f2tf(ps[(wband + g + 8)*FPT + kf*8 + tig]);
            pa[2] = f2tf(ps[(wband + g    )*FPT + kf*8 + tig + 4]);
            pa[3] = f2tf(ps[(wband + g + 8)*FPT + kf*8 + tig + 4]);
            #pragma unroll
            for (int nf = 0; nf < 8; nf++) {
                uint32_t bv[2];
                bv[0] = f2tf(vts[(nf*8 + g)*FPT + kf*8 + tig]);
                bv[1] = f2tf(vts[(nf*8 + g)*FPT + kf*8 + tig + 4]);
                mma8(o[nf], pa, bv);
            }
        }
        __syncwarp();  // ps reads done before next iter overwrites
    }

    // epilogue: O / l  -> g_ao [B,N,C], c = h*64 + d
    const float inv0 = 1.0f / l0;
    const float inv1 = 1.0f / l1;
    const int n0 = qtile*64 + wband + g;
    const int n1 = n0 + 8;
    #pragma unroll
    for (int nf = 0; nf < 8; nf++) {
        const int d = h*64 + nf*8 + 2*tig;
        float2 w0; w0.x = o[nf][0]*inv0; w0.y = o[nf][1]*inv0;
        float2 w1; w1.x = o[nf][2]*inv1; w1.y = o[nf][3]*inv1;
        *(float2*)&g_ao[((size_t)b*N_ + n0)*C_ + d] = w0;
        *(float2*)&g_ao[((size_t)b*N_ + n1)*C_ + d] = w1;
    }
}

// ---------------------------------------------------------------------------
extern "C" void kernel_launch(void* const* d_in, const int* in_sizes, int n_in,
                              void* d_out, int out_size)
{
    const float* x     = (const float*)d_in[0];   // [B,N,C]
    const float* wqkv  = (const float*)d_in[1];   // [3C,C]
    const float* wproj = (const float*)d_in[2];   // [C,C]
    float* out = (float*)d_out;                   // [B,N,C]

    // 1) QKV GEMM -> q/k/v [B,H,N,D]
    {
        dim3 grid(3*C_/128, (B_*N_)/128);   // (18, 64)
        gemm_tf32<0><<<grid, 256>>>(x, wqkv, nullptr, B_*N_, 3*C_, C_);
    }

    // 2) LayerNorm on q (*SCALE) and k
    {
        const int warps = 2 * BH_ * N_;
        const int blocks = (warps * 32 + 255) / 256;
        ln_kernel<<<blocks, 256>>>();
    }

    // 3) Flash attention (tf32 mma) -> g_ao
    {
        const int smem_bytes = 4 * 64 * FPT * (int)sizeof(float);  // 69632
        cudaFuncSetAttribute(flash_tf32,
                             cudaFuncAttributeMaxDynamicSharedMemorySize, smem_bytes);
        dim3 grid(N_/64, BH_);   // (16, 96)
        flash_tf32<<<grid, 128, smem_bytes>>>();
    }

    // 4) Output projection
    {
        dim3 grid(C_/128, (B_*N_)/128);     // (6, 64)
        gemm_tf32<1><<<grid, 256>>>(nullptr, wproj, out, B_*N_, C_, C_);
    }
}